// round 16
// baseline (speedup 1.0000x reference)
#include <cuda_runtime.h>
#include <cuda_bf16.h>
#include <math.h>
#include <stdint.h>

#define BB 8
#define DD 64
#define HH 128
#define WW 256

// ---------------- scratch (static device globals) ----------------
// ONLY referenced from device code (host-side symbol use = host shadow under ATS!)
// Activations stored as PRE-SPLIT bf16 hi/lo planes (hi = truncate, lo = rn residual).
__device__ uint16_t g_xh_hi[(size_t)WW * HH * BB * DD];   // [w][h*8+b][64]
__device__ uint16_t g_xh_lo[(size_t)WW * HH * BB * DD];
__device__ uint16_t g_vb_hi[(size_t)HH * WW * BB * 128];  // [h][w*8+b][128]
__device__ uint16_t g_vb_lo[(size_t)HH * WW * BB * 128];
__device__ float g_vout[(size_t)HH * WW * BB * 128];      // [h][w*8+b][128]
__device__ float g_gx[(size_t)2 * 262144 * 256];          // [dir][token][perm gate 4j+g], bias folded

__device__ __forceinline__ uint32_t smem_u32(const void* p) {
    uint32_t a;
    asm("{ .reg .u64 t; cvta.to.shared.u64 t, %1; cvt.u32.u64 %0, t; }" : "=r"(a) : "l"(p));
    return a;
}

__device__ __forceinline__ void cp_async16(void* dst, const void* src) {
    asm volatile("cp.async.cg.shared.global [%0], [%1], 16;"
                 :: "r"(smem_u32(dst)), "l"(src) : "memory");
}

__device__ __forceinline__ void mma_bf16(float* c, const uint32_t* a, const uint32_t* b) {
    asm volatile(
        "mma.sync.aligned.m16n8k16.row.col.f32.bf16.bf16.f32 "
        "{%0,%1,%2,%3}, {%4,%5,%6,%7}, {%8,%9}, {%0,%1,%2,%3};"
        : "+f"(c[0]), "+f"(c[1]), "+f"(c[2]), "+f"(c[3])
        : "r"(a[0]), "r"(a[1]), "r"(a[2]), "r"(a[3]), "r"(b[0]), "r"(b[1]));
}

__device__ __forceinline__ float tanh_ap(float x) {
    float y;
    asm("tanh.approx.f32 %0, %1;" : "=f"(y) : "f"(x));
    return y;
}

__device__ __forceinline__ uint32_t pack_bf16x2(float a, float b) {
    uint32_t r;
    asm("{ .reg .b16 lo, hi;\n\t"
        "cvt.rn.bf16.f32 lo, %1;\n\t"
        "cvt.rn.bf16.f32 hi, %2;\n\t"
        "mov.b32 %0, {lo, hi}; }"
        : "=r"(r) : "f"(a), "f"(b));
    return r;
}

// hi = truncated-bf16 (integer bit ops), lo = rn-bf16 of exact residual
__device__ __forceinline__ void split4(float4 v, uint2& hi, uint2& lo) {
    uint32_t ux = __float_as_uint(v.x), uy = __float_as_uint(v.y);
    uint32_t uz = __float_as_uint(v.z), uw = __float_as_uint(v.w);
    hi.x = (ux >> 16) | (uy & 0xFFFF0000u);
    hi.y = (uz >> 16) | (uw & 0xFFFF0000u);
    float lx = v.x - __uint_as_float(ux & 0xFFFF0000u);
    float ly = v.y - __uint_as_float(uy & 0xFFFF0000u);
    float lz = v.z - __uint_as_float(uz & 0xFFFF0000u);
    float lw = v.w - __uint_as_float(uw & 0xFFFF0000u);
    lo.x = pack_bf16x2(lx, ly);
    lo.y = pack_bf16x2(lz, lw);
}

__device__ __forceinline__ void split1(float x, uint16_t& h, uint16_t& l) {
    uint32_t u = __float_as_uint(x);
    h = (uint16_t)(u >> 16);
    float r = x - __uint_as_float(u & 0xFFFF0000u);
    uint16_t lb;
    asm("cvt.rn.bf16.f32 %0, %1;" : "=h"(lb) : "f"(r));
    l = lb;
}

// ---------------- transposes ----------------
// img[b][d][h][w] -> pre-split planes g_xh_{hi,lo}[w][h*8+b][d]
__global__ void transpose_in_k(const float* __restrict__ img) {
    __shared__ float tile[32][33];
    const int tx = threadIdx.x, ty = threadIdx.y;
    const int b = blockIdx.z & 7, h = blockIdx.z >> 3;
    const int w0 = blockIdx.x * 32, d0 = blockIdx.y * 32;
#pragma unroll
    for (int i = 0; i < 32; i += 8) {
        int d = d0 + ty + i;
        tile[ty + i][tx] = img[(((size_t)b * DD + d) * HH + h) * WW + w0 + tx];
    }
    __syncthreads();
#pragma unroll
    for (int i = 0; i < 32; i += 8) {
        int w = w0 + ty + i;
        float v = tile[tx][ty + i];
        uint16_t hb, lb;
        split1(v, hb, lb);
        size_t idx = ((size_t)w * (HH * BB) + blockIdx.z) * DD + d0 + tx;
        g_xh_hi[idx] = hb;
        g_xh_lo[idx] = lb;
    }
}

__global__ void transpose_out_k(float* __restrict__ out) {
    __shared__ float tile[32][33];
    const int tx = threadIdx.x, ty = threadIdx.y;
    const int b = blockIdx.z & 7, h = blockIdx.z >> 3;
    const int w0 = blockIdx.x * 32, c0 = blockIdx.y * 32;
#pragma unroll
    for (int i = 0; i < 32; i += 8) {
        int w = w0 + ty + i;
        tile[ty + i][tx] =
            g_vout[(size_t)h * (WW * BB * 128) + ((size_t)w * BB + b) * 128 + c0 + tx];
    }
    __syncthreads();
#pragma unroll
    for (int i = 0; i < 32; i += 8) {
        int c = c0 + ty + i;
        out[(((size_t)b * 128 + c) * HH + h) * WW + w0 + tx] = tile[tx][ty + i];
    }
}

// ---------------- gx GEMM: gx[dir][token][perm 4j+g] = X @ Wih^T + bias ----------------
// A tiles cp.async'd directly from pre-split bf16 planes into double-buffered
// padded smem (no fp32 stage, no conversion). Weights stationary in smem.
template <int K, bool VERT>
__global__ void __launch_bounds__(256, 1)
gx_gemm(const float* __restrict__ WF, const float* __restrict__ WB,
        const float* __restrict__ bihF, const float* __restrict__ bhhF,
        const float* __restrict__ bihB, const float* __restrict__ bhhB, int ntiles) {
    constexpr int SA = K + 8;
    extern __shared__ uint16_t smu[];
    uint16_t* A0hi = smu;                  // 128*SA each
    uint16_t* A0lo = A0hi + 128 * SA;
    uint16_t* A1hi = A0lo + 128 * SA;
    uint16_t* A1lo = A1hi + 128 * SA;
    uint16_t* Bhi = A1lo + 128 * SA;
    uint16_t* Blo = Bhi + 128 * SA;
    float* bsum = (float*)(Blo + 128 * SA);   // 128

    const uint16_t* Xhi = VERT ? g_vb_hi : g_xh_hi;
    const uint16_t* Xlo = VERT ? g_vb_lo : g_xh_lo;

    const int tid = threadIdx.x;
    const int warp = tid >> 5;
    const int lane = tid & 31;
    const int wm = warp & 3;
    const int wn = warp >> 2;
    const int half = blockIdx.y & 1;
    const int dir = blockIdx.y >> 1;

    const float* W = dir ? WB : WF;
    const float* bih = dir ? bihB : bihF;
    const float* bhh = dir ? bhhB : bhhF;
    float* gxo = g_gx + (size_t)dir * ((size_t)262144 * 256) + half * 128;

    // permuted stationary weights (hi/lo split once)
    for (int i = tid; i < 128 * (K / 4); i += 256) {
        int rr = i / (K / 4), c16 = i % (K / 4);
        int src = (rr & 3) * 64 + 32 * half + (rr >> 2);
        float4 v = ((const float4*)W)[src * (K / 4) + c16];
        uint2 hi, lo;
        split4(v, hi, lo);
        *(uint2*)&Bhi[rr * SA + c16 * 4] = hi;
        *(uint2*)&Blo[rr * SA + c16 * 4] = lo;
    }
    if (tid < 128) {
        int G = (tid & 3) * 64 + 32 * half + (tid >> 2);
        bsum[tid] = bih[G] + bhh[G];
    }

    const int qrow = lane >> 2;
    const int qk = (lane & 3) * 2;

    auto issue = [&](int t, uint16_t* dhi, uint16_t* dlo) {
        size_t base = (size_t)t * 128 * K;
        for (int i = tid; i < 128 * (K / 8); i += 256) {
            int row = i / (K / 8), c8 = (i % (K / 8)) * 8;
            cp_async16(dhi + row * SA + c8, Xhi + base + row * K + c8);
            cp_async16(dlo + row * SA + c8, Xlo + base + row * K + c8);
        }
        asm volatile("cp.async.commit_group;" ::: "memory");
    };

    int ti = blockIdx.x;
    int buf = 0;
    issue(ti, A0hi, A0lo);

    for (; ti < ntiles; ti += gridDim.x) {
        asm volatile("cp.async.wait_group 0;" ::: "memory");
        __syncthreads();   // tile ready; prior iteration's mma on other buf done
        uint16_t* Ahi = buf ? A1hi : A0hi;
        uint16_t* Alo = buf ? A1lo : A0lo;
        int tn = ti + gridDim.x;
        if (tn < ntiles) issue(tn, buf ? A0hi : A1hi, buf ? A0lo : A1lo);

        float c[2][8][4];
#pragma unroll
        for (int i = 0; i < 2; i++)
#pragma unroll
            for (int j = 0; j < 8; j++)
#pragma unroll
                for (int q = 0; q < 4; q++) c[i][j][q] = 0.0f;

#pragma unroll
        for (int kc = 0; kc < K / 16; kc++) {
            uint32_t Bh[4][4], Bl[4][4];
#pragma unroll
            for (int jp = 0; jp < 4; jp++) {
                int base = (wn * 64 + jp * 16 + qrow) * SA + kc * 16 + qk;
                Bh[jp][0] = *(const uint32_t*)&Bhi[base];
                Bh[jp][1] = *(const uint32_t*)&Bhi[base + 8];
                Bh[jp][2] = *(const uint32_t*)&Bhi[base + 8 * SA];
                Bh[jp][3] = *(const uint32_t*)&Bhi[base + 8 * SA + 8];
                Bl[jp][0] = *(const uint32_t*)&Blo[base];
                Bl[jp][1] = *(const uint32_t*)&Blo[base + 8];
                Bl[jp][2] = *(const uint32_t*)&Blo[base + 8 * SA];
                Bl[jp][3] = *(const uint32_t*)&Blo[base + 8 * SA + 8];
            }
#pragma unroll
            for (int ib = 0; ib < 2; ib++) {
                int base = (wm * 32 + ib * 16 + qrow) * SA + kc * 16 + qk;
                uint32_t Ah[4], Al[4];
                Ah[0] = *(const uint32_t*)&Ahi[base];
                Ah[1] = *(const uint32_t*)&Ahi[base + 8 * SA];
                Ah[2] = *(const uint32_t*)&Ahi[base + 8];
                Ah[3] = *(const uint32_t*)&Ahi[base + 8 * SA + 8];
                Al[0] = *(const uint32_t*)&Alo[base];
                Al[1] = *(const uint32_t*)&Alo[base + 8 * SA];
                Al[2] = *(const uint32_t*)&Alo[base + 8];
                Al[3] = *(const uint32_t*)&Alo[base + 8 * SA + 8];
#pragma unroll
                for (int jp = 0; jp < 4; jp++)
#pragma unroll
                    for (int h = 0; h < 2; h++) {
                        float* cc = c[ib][jp * 2 + h];
                        mma_bf16(cc, Ah, &Bh[jp][h * 2]);
                        mma_bf16(cc, Ah, &Bl[jp][h * 2]);
                        mma_bf16(cc, Al, &Bh[jp][h * 2]);
                    }
            }
        }

        const size_t token0 = (size_t)ti * 128;
#pragma unroll
        for (int ib = 0; ib < 2; ib++) {
            size_t row = token0 + wm * 32 + ib * 16 + qrow;
#pragma unroll
            for (int j = 0; j < 8; j++) {
                int col = wn * 64 + j * 8 + qk;
                float b0 = bsum[col], b1 = bsum[col + 1];
                *(float2*)&gxo[row * 256 + col] =
                    make_float2(c[ib][j][0] + b0, c[ib][j][1] + b1);
                *(float2*)&gxo[(row + 8) * 256 + col] =
                    make_float2(c[ib][j][2] + b0, c[ib][j][3] + b1);
            }
        }
        buf ^= 1;
    }
}

// ---------------- mma recurrence: gates_t = gx_t + h @ Whh'^T ----------------
// 512 threads / 16 warps; warp owns 16 perm-cols. Paired h layout (LDS.64),
// MUFU.TANH, running pointers, unroll-2 role swap, 3-way split chains (MT==1).
// Output: hR (VERT=false) writes pre-split bf16 planes; vR writes fp32 g_vout.
template <bool VERT, int T, int STOT, int NSEQ, int OT, int SDIV, int OHI>
__global__ void __launch_bounds__(512, 1)
lstm_recur_mma(const float* __restrict__ WhhF, const float* __restrict__ WhhB) {
    constexpr int MT = NSEQ / 16;
    constexpr bool SACC = (MT == 1);
    constexpr int SWW = 72;    // weight staging stride (bf16)
    constexpr int SW = 80;     // h-state stride (bf16)
    constexpr int NG = MT * 2;
    extern __shared__ char smraw[];
    uint16_t* WHi = (uint16_t*)smraw;            // weight staging (transient)
    uint16_t* WLo = WHi + 256 * SWW;
    uint16_t* hHi0 = (uint16_t*)smraw;           // h double buffers (alias staging)
    uint16_t* hLo0 = hHi0 + NSEQ * SW;
    uint16_t* hHi1 = hLo0 + NSEQ * SW;
    uint16_t* hLo1 = hHi1 + NSEQ * SW;

    const int tid = threadIdx.x;
    const int wn = tid >> 5;            // 0..15, warp owns perm cols [wn*16, wn*16+16)
    const int lane = tid & 31;
    const int qrow = lane >> 2;
    const int qk = (lane & 3) * 2;
    const int par = lane & 1;
    const int dir = blockIdx.y;
    const int s0 = blockIdx.x * NSEQ;

    const float* Whh = dir ? WhhB : WhhF;
    const float* gxd = g_gx + (size_t)dir * ((size_t)262144 * 256);

    // stage permuted Whh hi/lo
    for (int i = tid; i < 256 * 16; i += 512) {
        int rr = i >> 4, c16 = i & 15;
        int src = (rr & 3) * 64 + (rr >> 2);
        float4 v = ((const float4*)Whh)[src * 16 + c16];
        uint2 hi, lo;
        split4(v, hi, lo);
        *(uint2*)&WHi[rr * SWW + c16 * 4] = hi;
        *(uint2*)&WLo[rr * SWW + c16 * 4] = lo;
    }
    __syncthreads();

    uint32_t Bh[4][4], Bl[4][4];        // [kc][reg] for this warp's 16 cols
#pragma unroll
    for (int kc = 0; kc < 4; kc++) {
        int base = (wn * 16 + qrow) * SWW + kc * 16 + qk;
        Bh[kc][0] = *(const uint32_t*)&WHi[base];
        Bh[kc][1] = *(const uint32_t*)&WHi[base + 8];
        Bh[kc][2] = *(const uint32_t*)&WHi[base + 8 * SWW];
        Bh[kc][3] = *(const uint32_t*)&WHi[base + 8 * SWW + 8];
        Bl[kc][0] = *(const uint32_t*)&WLo[base];
        Bl[kc][1] = *(const uint32_t*)&WLo[base + 8];
        Bl[kc][2] = *(const uint32_t*)&WLo[base + 8 * SWW];
        Bl[kc][3] = *(const uint32_t*)&WLo[base + 8 * SWW + 8];
    }
    __syncthreads();   // done reading staging; alias as h buffers

    for (int i = tid; i < NSEQ * SW; i += 512) { hHi0[i] = 0; hLo0[i] = 0; }

    // running pointers + precomputed per-group offsets
    const int tt0 = dir ? (T - 1) : 0;
    const int dstep = dir ? -(STOT * 256) : (STOT * 256);
    const float* gp = gxd + ((size_t)tt0 * STOT + s0 + qrow) * 256 + wn * 16 + qk;
    const int dOT = dir ? -OT : OT;
    float* op = g_vout + (size_t)tt0 * OT + (size_t)dir * 64;      // vR path
    uint16_t* ophi = g_vb_hi + (size_t)tt0 * OT + (size_t)dir * 64; // hR path
    uint16_t* oplo = g_vb_lo + (size_t)tt0 * OT + (size_t)dir * 64;
    int ooff[NG], hwoff[NG];
#pragma unroll
    for (int mt = 0; mt < MT; mt++)
#pragma unroll
        for (int h8 = 0; h8 < 2; h8++) {
            int g = mt * 2 + h8;
            int j = wn * 4 + h8 * 2 + (qk >> 2);
            int myrow = mt * 16 + qrow + par * 8;
            int s = s0 + myrow;
            ooff[g] = (s / SDIV) * OHI + (s % SDIV) * 128 + j;
            // paired layout position of hidden unit j:
            int j16 = j & 15, blk = j >> 4;
            int m = j16 >> 1, odd = j16 & 1;
            int sl = (m < 4) ? (m << 1) : (((m - 4) << 1) + 1);
            hwoff[g] = myrow * SW + blk * 16 + sl * 2 + odd;
        }
    const int abase = qrow * SW + (lane & 3) * 4;   // u16 idx; per kc add kc*16

    float cur[MT][2][4], nxt[MT][2][4];
#pragma unroll
    for (int mt = 0; mt < MT; mt++)
#pragma unroll
        for (int h8 = 0; h8 < 2; h8++) {
            const float* p = gp + mt * (16 * 256) + h8 * 8;
            float2 ab = *(const float2*)p;
            float2 cd = *(const float2*)(p + 8 * 256);
            cur[mt][h8][0] = ab.x; cur[mt][h8][1] = ab.y;
            cur[mt][h8][2] = cd.x; cur[mt][h8][3] = cd.y;
        }
    gp += dstep;

    float creg[MT][2];
#pragma unroll
    for (int mt = 0; mt < MT; mt++)
#pragma unroll
        for (int h8 = 0; h8 < 2; h8++) creg[mt][h8] = 0.0f;
    __syncthreads();

#define LSTM_STEP(RHI, RLO, WHI_, WLO_, CUR, NXT, TQ)                            \
    do {                                                                         \
        if ((TQ) + 1 < T) {                                                      \
            _Pragma("unroll") for (int mt = 0; mt < MT; mt++)                    \
            _Pragma("unroll") for (int h8 = 0; h8 < 2; h8++) {                   \
                const float* p = gp + mt * (16 * 256) + h8 * 8;                  \
                float2 ab = *(const float2*)p;                                   \
                float2 cd = *(const float2*)(p + 8 * 256);                       \
                NXT[mt][h8][0] = ab.x; NXT[mt][h8][1] = ab.y;                    \
                NXT[mt][h8][2] = cd.x; NXT[mt][h8][3] = cd.y;                    \
            }                                                                    \
        }                                                                        \
        float acc1[MT][2][4], acc2[MT][2][4];                                    \
        if (SACC) {                                                              \
            _Pragma("unroll") for (int mt = 0; mt < MT; mt++)                    \
            _Pragma("unroll") for (int h8 = 0; h8 < 2; h8++)                     \
            _Pragma("unroll") for (int q = 0; q < 4; q++) {                      \
                acc1[mt][h8][q] = 0.0f; acc2[mt][h8][q] = 0.0f;                  \
            }                                                                    \
        }                                                                        \
        _Pragma("unroll") for (int kc = 0; kc < 4; kc++) {                       \
            uint32_t Ah[MT][4], Al[MT][4];                                       \
            _Pragma("unroll") for (int mt = 0; mt < MT; mt++) {                  \
                int base = abase + mt * 16 * SW + kc * 16;                       \
                uint2 v0 = *(const uint2*)&RHI[base];                            \
                uint2 v1 = *(const uint2*)&RHI[base + 8 * SW];                   \
                Ah[mt][0] = v0.x; Ah[mt][2] = v0.y;                              \
                Ah[mt][1] = v1.x; Ah[mt][3] = v1.y;                              \
                uint2 w0 = *(const uint2*)&RLO[base];                            \
                uint2 w1 = *(const uint2*)&RLO[base + 8 * SW];                   \
                Al[mt][0] = w0.x; Al[mt][2] = w0.y;                              \
                Al[mt][1] = w1.x; Al[mt][3] = w1.y;                              \
            }                                                                    \
            _Pragma("unroll") for (int mt = 0; mt < MT; mt++)                    \
            _Pragma("unroll") for (int h8 = 0; h8 < 2; h8++) {                   \
                mma_bf16(CUR[mt][h8], Ah[mt], &Bh[kc][h8 * 2]);                  \
                float* t1 = SACC ? acc1[mt][h8] : CUR[mt][h8];                   \
                float* t2 = SACC ? acc2[mt][h8] : CUR[mt][h8];                   \
                mma_bf16(t1, Ah[mt], &Bl[kc][h8 * 2]);                           \
                mma_bf16(t2, Al[mt], &Bh[kc][h8 * 2]);                           \
            }                                                                    \
        }                                                                        \
        _Pragma("unroll") for (int mt = 0; mt < MT; mt++)                        \
        _Pragma("unroll") for (int h8 = 0; h8 < 2; h8++) {                       \
            int g = mt * 2 + h8;                                                 \
            float cc0 = CUR[mt][h8][0], cc1 = CUR[mt][h8][1];                    \
            float cc2 = CUR[mt][h8][2], cc3 = CUR[mt][h8][3];                    \
            if (SACC) {                                                          \
                cc0 += acc1[mt][h8][0] + acc2[mt][h8][0];                        \
                cc1 += acc1[mt][h8][1] + acc2[mt][h8][1];                        \
                cc2 += acc1[mt][h8][2] + acc2[mt][h8][2];                        \
                cc3 += acc1[mt][h8][3] + acc2[mt][h8][3];                        \
            }                                                                    \
            float s0v = par ? cc0 : cc2;                                         \
            float s1v = par ? cc1 : cc3;                                         \
            float r0 = __shfl_xor_sync(0xFFFFFFFFu, s0v, 1);                     \
            float r1 = __shfl_xor_sync(0xFFFFFFFFu, s1v, 1);                     \
            float iv, fv, gv, ov;                                                \
            if (!par) { iv = cc0; fv = cc1; gv = r0; ov = r1; }                  \
            else      { iv = r0;  fv = r1;  gv = cc2; ov = cc3; }                \
            float si = fmaf(0.5f, tanh_ap(0.5f * iv), 0.5f);                     \
            float sf = fmaf(0.5f, tanh_ap(0.5f * fv), 0.5f);                     \
            float so = fmaf(0.5f, tanh_ap(0.5f * ov), 0.5f);                     \
            float tg = tanh_ap(gv);                                              \
            float cst = sf * creg[mt][h8] + si * tg;                             \
            creg[mt][h8] = cst;                                                  \
            float hv = so * tanh_ap(cst);                                        \
            uint16_t hb, lb;                                                     \
            split1(hv, hb, lb);                                                  \
            WHI_[hwoff[g]] = hb;                                                 \
            WLO_[hwoff[g]] = lb;                                                 \
            if (VERT) {                                                          \
                op[ooff[g]] = hv;                                                \
            } else {                                                             \
                ophi[ooff[g]] = hb;                                              \
                oplo[ooff[g]] = lb;                                              \
            }                                                                    \
        }                                                                        \
        gp += dstep;                                                             \
        op += dOT; ophi += dOT; oplo += dOT;                                     \
        __syncthreads();                                                         \
    } while (0)

    for (int t = 0; t < T; t += 2) {
        LSTM_STEP(hHi0, hLo0, hHi1, hLo1, cur, nxt, t);
        LSTM_STEP(hHi1, hLo1, hHi0, hLo0, nxt, cur, t + 1);
    }
#undef LSTM_STEP
}

// ---------------- launch ----------------
extern "C" void kernel_launch(void* const* d_in, const int* in_sizes, int n_in,
                              void* d_out, int out_size) {
    const float* img    = (const float*)d_in[0];
    const float* hWihF  = (const float*)d_in[1];
    const float* hWhhF  = (const float*)d_in[2];
    const float* hbihF  = (const float*)d_in[3];
    const float* hbhhF  = (const float*)d_in[4];
    const float* hWihB  = (const float*)d_in[5];
    const float* hWhhB  = (const float*)d_in[6];
    const float* hbihB  = (const float*)d_in[7];
    const float* hbhhB  = (const float*)d_in[8];
    const float* vWihF  = (const float*)d_in[9];
    const float* vWhhF  = (const float*)d_in[10];
    const float* vbihF  = (const float*)d_in[11];
    const float* vbhhF  = (const float*)d_in[12];
    const float* vWihB  = (const float*)d_in[13];
    const float* vWhhB  = (const float*)d_in[14];
    const float* vbihB  = (const float*)d_in[15];
    const float* vbhhB  = (const float*)d_in[16];
    float* out = (float*)d_out;

    auto hG = gx_gemm<64, false>;
    auto vG = gx_gemm<128, true>;
    auto hR = lstm_recur_mma<false, 256, 1024, 16, 1024, 8, 262144>;
    auto vR = lstm_recur_mma<true, 128, 2048, 32, 262144, (1 << 28), 0>;

    const int smemHG = 6 * 128 * (64 + 8) * 2 + 512;    // 111,104 B
    const int smemVG = 6 * 128 * (128 + 8) * 2 + 512;   // 209,408 B
    const int smemR = 2 * 256 * 72 * 2;                 //  73,728 B
    cudaFuncSetAttribute(hG, cudaFuncAttributeMaxDynamicSharedMemorySize, smemHG);
    cudaFuncSetAttribute(vG, cudaFuncAttributeMaxDynamicSharedMemorySize, smemVG);
    cudaFuncSetAttribute(hR, cudaFuncAttributeMaxDynamicSharedMemorySize, smemR);
    cudaFuncSetAttribute(vR, cudaFuncAttributeMaxDynamicSharedMemorySize, smemR);

    // 1) img -> pre-split g_xh planes
    transpose_in_k<<<dim3(WW / 32, DD / 32, HH * BB), dim3(32, 8)>>>(img);

    // 2) gxh (permuted, bias folded; bf16 planes streamed in)
    hG<<<dim3(37, 4), 256, smemHG>>>(hWihF, hWihB, hbihF, hbhhF, hbihB, hbhhB, 2048);

    // 3) horizontal mma recurrence -> pre-split g_vb planes
    hR<<<dim3(64, 2), 512, smemR>>>(hWhhF, hWhhB);

    // 4) gxv (bf16 planes streamed in)  [ncu 4th-launch capture lands here]
    vG<<<dim3(37, 4), 256, smemVG>>>(vWihF, vWihB, vbihF, vbhhF, vbihB, vbhhB, 2048);

    // 5) vertical mma recurrence -> g_vout (fp32)
    vR<<<dim3(64, 2), 512, smemR>>>(vWhhF, vWhhB);

    // 6) g_vout -> out
    transpose_out_k<<<dim3(WW / 32, 128 / 32, HH * BB), dim3(32, 8)>>>(out);
}

// round 17
// speedup vs baseline: 1.1056x; 1.1056x over previous
#include <cuda_runtime.h>
#include <cuda_bf16.h>
#include <math.h>
#include <stdint.h>

#define BB 8
#define DD 64
#define HH 128
#define WW 256

// ---------------- scratch (static device globals) ----------------
// ONLY referenced from device code (host-side symbol use = host shadow under ATS!)
// g_xh_pack: packed bf16 split planes, word = hi | lo<<16 (hi=truncate, lo=rn residual)
__device__ uint32_t g_xh_pack[(size_t)WW * HH * BB * DD];  // [w][h*8+b][64]
__device__ float g_vbuf[(size_t)HH * WW * BB * 128];       // [h][w*8+b][128]
__device__ float g_vout[(size_t)HH * WW * BB * 128];       // [h][w*8+b][128]
__device__ float g_gx[(size_t)2 * 262144 * 256];           // [dir][token][perm gate 4j+g], bias folded

__device__ __forceinline__ uint32_t smem_u32(const void* p) {
    uint32_t a;
    asm("{ .reg .u64 t; cvta.to.shared.u64 t, %1; cvt.u32.u64 %0, t; }" : "=r"(a) : "l"(p));
    return a;
}

__device__ __forceinline__ void cp_async16(void* dst, const void* src) {
    asm volatile("cp.async.cg.shared.global [%0], [%1], 16;"
                 :: "r"(smem_u32(dst)), "l"(src) : "memory");
}

__device__ __forceinline__ void mma_bf16(float* c, const uint32_t* a, const uint32_t* b) {
    asm volatile(
        "mma.sync.aligned.m16n8k16.row.col.f32.bf16.bf16.f32 "
        "{%0,%1,%2,%3}, {%4,%5,%6,%7}, {%8,%9}, {%0,%1,%2,%3};"
        : "+f"(c[0]), "+f"(c[1]), "+f"(c[2]), "+f"(c[3])
        : "r"(a[0]), "r"(a[1]), "r"(a[2]), "r"(a[3]), "r"(b[0]), "r"(b[1]));
}

__device__ __forceinline__ float tanh_ap(float x) {
    float y;
    asm("tanh.approx.f32 %0, %1;" : "=f"(y) : "f"(x));
    return y;
}

__device__ __forceinline__ uint32_t prmt(uint32_t a, uint32_t b, uint32_t sel) {
    uint32_t r;
    asm("prmt.b32 %0, %1, %2, %3;" : "=r"(r) : "r"(a), "r"(b), "r"(sel));
    return r;
}

__device__ __forceinline__ uint32_t pack_bf16x2(float a, float b) {
    uint32_t r;
    asm("{ .reg .b16 lo, hi;\n\t"
        "cvt.rn.bf16.f32 lo, %1;\n\t"
        "cvt.rn.bf16.f32 hi, %2;\n\t"
        "mov.b32 %0, {lo, hi}; }"
        : "=r"(r) : "f"(a), "f"(b));
    return r;
}

// hi = truncated-bf16 (integer bit ops), lo = rn-bf16 of exact residual
__device__ __forceinline__ void split4(float4 v, uint2& hi, uint2& lo) {
    uint32_t ux = __float_as_uint(v.x), uy = __float_as_uint(v.y);
    uint32_t uz = __float_as_uint(v.z), uw = __float_as_uint(v.w);
    hi.x = (ux >> 16) | (uy & 0xFFFF0000u);
    hi.y = (uz >> 16) | (uw & 0xFFFF0000u);
    float lx = v.x - __uint_as_float(ux & 0xFFFF0000u);
    float ly = v.y - __uint_as_float(uy & 0xFFFF0000u);
    float lz = v.z - __uint_as_float(uz & 0xFFFF0000u);
    float lw = v.w - __uint_as_float(uw & 0xFFFF0000u);
    lo.x = pack_bf16x2(lx, ly);
    lo.y = pack_bf16x2(lz, lw);
}

__device__ __forceinline__ void split1(float x, uint16_t& h, uint16_t& l) {
    uint32_t u = __float_as_uint(x);
    h = (uint16_t)(u >> 16);
    float r = x - __uint_as_float(u & 0xFFFF0000u);
    uint16_t lb;
    asm("cvt.rn.bf16.f32 %0, %1;" : "=h"(lb) : "f"(r));
    l = lb;
}

// capture-alignment probe: keeps ncu -c 1 on the hR launch (#4). Does nothing.
__global__ void probe_k() {}

// ---------------- transposes ----------------
// img[b][d][h][w] -> packed split plane g_xh_pack[w][h*8+b][d]
__global__ void transpose_in_k(const float* __restrict__ img) {
    __shared__ float tile[32][33];
    const int tx = threadIdx.x, ty = threadIdx.y;
    const int b = blockIdx.z & 7, h = blockIdx.z >> 3;
    const int w0 = blockIdx.x * 32, d0 = blockIdx.y * 32;
#pragma unroll
    for (int i = 0; i < 32; i += 8) {
        int d = d0 + ty + i;
        tile[ty + i][tx] = img[(((size_t)b * DD + d) * HH + h) * WW + w0 + tx];
    }
    __syncthreads();
#pragma unroll
    for (int i = 0; i < 32; i += 8) {
        int w = w0 + ty + i;
        float v = tile[tx][ty + i];
        uint16_t hb, lb;
        split1(v, hb, lb);
        g_xh_pack[((size_t)w * (HH * BB) + blockIdx.z) * DD + d0 + tx] =
            (uint32_t)hb | ((uint32_t)lb << 16);
    }
}

__global__ void transpose_out_k(float* __restrict__ out) {
    __shared__ float tile[32][33];
    const int tx = threadIdx.x, ty = threadIdx.y;
    const int b = blockIdx.z & 7, h = blockIdx.z >> 3;
    const int w0 = blockIdx.x * 32, c0 = blockIdx.y * 32;
#pragma unroll
    for (int i = 0; i < 32; i += 8) {
        int w = w0 + ty + i;
        tile[ty + i][tx] =
            g_vout[(size_t)h * (WW * BB * 128) + ((size_t)w * BB + b) * 128 + c0 + tx];
    }
    __syncthreads();
#pragma unroll
    for (int i = 0; i < 32; i += 8) {
        int c = c0 + ty + i;
        out[(((size_t)b * 128 + c) * HH + h) * WW + w0 + tx] = tile[tx][ty + i];
    }
}

// ---------------- gx GEMM: gx[dir][token][perm 4j+g] = X @ Wih^T + bias ----------------
// PACKED=true: stage holds packed split u32 words, PRMT unpack (hG).
// PACKED=false: stage holds fp32, split4 conversion (vG reading g_vbuf).
template <int K, bool PACKED>
__global__ void __launch_bounds__(256, 1)
gx_gemm(const float* __restrict__ WF, const float* __restrict__ WB,
        const float* __restrict__ bihF, const float* __restrict__ bhhF,
        const float* __restrict__ bihB, const float* __restrict__ bhhB, int ntiles) {
    constexpr int SA = K + 8;
    extern __shared__ uint32_t smw[];
    uint32_t* stage = smw;                            // 128*K words (fp32 or packed)
    uint16_t* Ahi = (uint16_t*)(stage + 128 * K);     // 128*SA each
    uint16_t* Alo = Ahi + 128 * SA;
    uint16_t* Bhi = Alo + 128 * SA;
    uint16_t* Blo = Bhi + 128 * SA;
    float* bsum = (float*)(Blo + 128 * SA);           // 128

    const uint32_t* Xsrc = PACKED ? g_xh_pack : (const uint32_t*)g_vbuf;

    const int tid = threadIdx.x;
    const int warp = tid >> 5;
    const int lane = tid & 31;
    const int wm = warp & 3;
    const int wn = warp >> 2;
    const int half = blockIdx.y & 1;
    const int dir = blockIdx.y >> 1;

    const float* W = dir ? WB : WF;
    const float* bih = dir ? bihB : bihF;
    const float* bhh = dir ? bhhB : bhhF;
    float* gxo = g_gx + (size_t)dir * ((size_t)262144 * 256) + half * 128;

    // permuted stationary weights (hi/lo split once)
    for (int i = tid; i < 128 * (K / 4); i += 256) {
        int rr = i / (K / 4), c16 = i % (K / 4);
        int src = (rr & 3) * 64 + 32 * half + (rr >> 2);
        float4 v = ((const float4*)W)[src * (K / 4) + c16];
        uint2 hi, lo;
        split4(v, hi, lo);
        *(uint2*)&Bhi[rr * SA + c16 * 4] = hi;
        *(uint2*)&Blo[rr * SA + c16 * 4] = lo;
    }
    if (tid < 128) {
        int G = (tid & 3) * 64 + 32 * half + (tid >> 2);
        bsum[tid] = bih[G] + bhh[G];
    }

    const int qrow = lane >> 2;
    const int qk = (lane & 3) * 2;

    int ti = blockIdx.x;
    {
        const uint32_t* Xt = Xsrc + (size_t)ti * 128 * K;
        for (int i = tid; i < 128 * K / 4; i += 256)
            cp_async16(stage + i * 4, Xt + i * 4);
        asm volatile("cp.async.commit_group;" ::: "memory");
    }

    for (; ti < ntiles; ti += gridDim.x) {
        asm volatile("cp.async.wait_group 0;" ::: "memory");
        __syncthreads();
        // convert stage -> hi/lo bf16 smem
        for (int i = tid; i < 128 * K / 4; i += 256) {
            int row = i / (K / 4), c4 = (i % (K / 4)) * 4;
            uint2 hi, lo;
            if (PACKED) {
                uint4 w = *(uint4*)&stage[i * 4];
                hi.x = prmt(w.x, w.y, 0x5410);   // (hi0, hi1)
                hi.y = prmt(w.z, w.w, 0x5410);   // (hi2, hi3)
                lo.x = prmt(w.x, w.y, 0x7632);   // (lo0, lo1)
                lo.y = prmt(w.z, w.w, 0x7632);   // (lo2, lo3)
            } else {
                float4 v = *(float4*)&stage[i * 4];
                split4(v, hi, lo);
            }
            *(uint2*)&Ahi[row * SA + c4] = hi;
            *(uint2*)&Alo[row * SA + c4] = lo;
        }
        __syncthreads();
        if (ti + (int)gridDim.x < ntiles) {
            const uint32_t* Xt = Xsrc + (size_t)(ti + gridDim.x) * 128 * K;
            for (int i = tid; i < 128 * K / 4; i += 256)
                cp_async16(stage + i * 4, Xt + i * 4);
            asm volatile("cp.async.commit_group;" ::: "memory");
        }

        float c[2][8][4];
#pragma unroll
        for (int i = 0; i < 2; i++)
#pragma unroll
            for (int j = 0; j < 8; j++)
#pragma unroll
                for (int q = 0; q < 4; q++) c[i][j][q] = 0.0f;

#pragma unroll
        for (int kc = 0; kc < K / 16; kc++) {
            uint32_t Bh[4][4], Bl[4][4];
#pragma unroll
            for (int jp = 0; jp < 4; jp++) {
                int base = (wn * 64 + jp * 16 + qrow) * SA + kc * 16 + qk;
                Bh[jp][0] = *(const uint32_t*)&Bhi[base];
                Bh[jp][1] = *(const uint32_t*)&Bhi[base + 8];
                Bh[jp][2] = *(const uint32_t*)&Bhi[base + 8 * SA];
                Bh[jp][3] = *(const uint32_t*)&Bhi[base + 8 * SA + 8];
                Bl[jp][0] = *(const uint32_t*)&Blo[base];
                Bl[jp][1] = *(const uint32_t*)&Blo[base + 8];
                Bl[jp][2] = *(const uint32_t*)&Blo[base + 8 * SA];
                Bl[jp][3] = *(const uint32_t*)&Blo[base + 8 * SA + 8];
            }
#pragma unroll
            for (int ib = 0; ib < 2; ib++) {
                int base = (wm * 32 + ib * 16 + qrow) * SA + kc * 16 + qk;
                uint32_t Ah[4], Al[4];
                Ah[0] = *(const uint32_t*)&Ahi[base];
                Ah[1] = *(const uint32_t*)&Ahi[base + 8 * SA];
                Ah[2] = *(const uint32_t*)&Ahi[base + 8];
                Ah[3] = *(const uint32_t*)&Ahi[base + 8 * SA + 8];
                Al[0] = *(const uint32_t*)&Alo[base];
                Al[1] = *(const uint32_t*)&Alo[base + 8 * SA];
                Al[2] = *(const uint32_t*)&Alo[base + 8];
                Al[3] = *(const uint32_t*)&Alo[base + 8 * SA + 8];
#pragma unroll
                for (int jp = 0; jp < 4; jp++)
#pragma unroll
                    for (int h = 0; h < 2; h++) {
                        float* cc = c[ib][jp * 2 + h];
                        mma_bf16(cc, Ah, &Bh[jp][h * 2]);
                        mma_bf16(cc, Ah, &Bl[jp][h * 2]);
                        mma_bf16(cc, Al, &Bh[jp][h * 2]);
                    }
            }
        }

        const size_t token0 = (size_t)ti * 128;
#pragma unroll
        for (int ib = 0; ib < 2; ib++) {
            size_t row = token0 + wm * 32 + ib * 16 + qrow;
#pragma unroll
            for (int j = 0; j < 8; j++) {
                int col = wn * 64 + j * 8 + qk;
                float b0 = bsum[col], b1 = bsum[col + 1];
                *(float2*)&gxo[row * 256 + col] =
                    make_float2(c[ib][j][0] + b0, c[ib][j][1] + b1);
                *(float2*)&gxo[(row + 8) * 256 + col] =
                    make_float2(c[ib][j][2] + b0, c[ib][j][3] + b1);
            }
        }
        __syncthreads();
    }
}

// ---------------- mma recurrence: gates_t = gx_t + h @ Whh'^T ----------------
// 512 threads / 16 warps; each warp owns 16 perm-cols. Paired h layout
// (LDS.64 fragment loads), MUFU.TANH, running pointers, unroll-2 role swap,
// 3-way split accumulator chains when MT==1.  [identical to the R14 kernel]
template <bool VERT, int T, int STOT, int NSEQ, int OT, int SDIV, int OHI>
__global__ void __launch_bounds__(512, 1)
lstm_recur_mma(const float* __restrict__ WhhF, const float* __restrict__ WhhB) {
    constexpr int MT = NSEQ / 16;
    constexpr bool SACC = (MT == 1);
    constexpr int SWW = 72;    // weight staging stride (bf16)
    constexpr int SW = 80;     // h-state stride (bf16)
    constexpr int NG = MT * 2;
    extern __shared__ char smraw[];
    uint16_t* WHi = (uint16_t*)smraw;            // weight staging (transient)
    uint16_t* WLo = WHi + 256 * SWW;
    uint16_t* hHi0 = (uint16_t*)smraw;           // h double buffers (alias staging)
    uint16_t* hLo0 = hHi0 + NSEQ * SW;
    uint16_t* hHi1 = hLo0 + NSEQ * SW;
    uint16_t* hLo1 = hHi1 + NSEQ * SW;

    const int tid = threadIdx.x;
    const int wn = tid >> 5;            // 0..15, warp owns perm cols [wn*16, wn*16+16)
    const int lane = tid & 31;
    const int qrow = lane >> 2;
    const int qk = (lane & 3) * 2;
    const int par = lane & 1;
    const int dir = blockIdx.y;
    const int s0 = blockIdx.x * NSEQ;

    const float* Whh = dir ? WhhB : WhhF;
    const float* gxd = g_gx + (size_t)dir * ((size_t)262144 * 256);
    float* outbuf = VERT ? g_vout : g_vbuf;

    // stage permuted Whh hi/lo
    for (int i = tid; i < 256 * 16; i += 512) {
        int rr = i >> 4, c16 = i & 15;
        int src = (rr & 3) * 64 + (rr >> 2);
        float4 v = ((const float4*)Whh)[src * 16 + c16];
        uint2 hi, lo;
        split4(v, hi, lo);
        *(uint2*)&WHi[rr * SWW + c16 * 4] = hi;
        *(uint2*)&WLo[rr * SWW + c16 * 4] = lo;
    }
    __syncthreads();

    uint32_t Bh[4][4], Bl[4][4];        // [kc][reg] for this warp's 16 cols
#pragma unroll
    for (int kc = 0; kc < 4; kc++) {
        int base = (wn * 16 + qrow) * SWW + kc * 16 + qk;
        Bh[kc][0] = *(const uint32_t*)&WHi[base];
        Bh[kc][1] = *(const uint32_t*)&WHi[base + 8];
        Bh[kc][2] = *(const uint32_t*)&WHi[base + 8 * SWW];
        Bh[kc][3] = *(const uint32_t*)&WHi[base + 8 * SWW + 8];
        Bl[kc][0] = *(const uint32_t*)&WLo[base];
        Bl[kc][1] = *(const uint32_t*)&WLo[base + 8];
        Bl[kc][2] = *(const uint32_t*)&WLo[base + 8 * SWW];
        Bl[kc][3] = *(const uint32_t*)&WLo[base + 8 * SWW + 8];
    }
    __syncthreads();   // done reading staging; alias as h buffers

    for (int i = tid; i < NSEQ * SW; i += 512) { hHi0[i] = 0; hLo0[i] = 0; }

    // running pointers + precomputed per-group offsets
    const int tt0 = dir ? (T - 1) : 0;
    const int dstep = dir ? -(STOT * 256) : (STOT * 256);
    const float* gp = gxd + ((size_t)tt0 * STOT + s0 + qrow) * 256 + wn * 16 + qk;
    const int dOT = dir ? -OT : OT;
    float* op = outbuf + (size_t)tt0 * OT + (size_t)dir * 64;
    int ooff[NG], hwoff[NG];
#pragma unroll
    for (int mt = 0; mt < MT; mt++)
#pragma unroll
        for (int h8 = 0; h8 < 2; h8++) {
            int g = mt * 2 + h8;
            int j = wn * 4 + h8 * 2 + (qk >> 2);
            int myrow = mt * 16 + qrow + par * 8;
            int s = s0 + myrow;
            ooff[g] = (s / SDIV) * OHI + (s % SDIV) * 128 + j;
            // paired layout position of hidden unit j:
            int j16 = j & 15, blk = j >> 4;
            int m = j16 >> 1, odd = j16 & 1;
            int sl = (m < 4) ? (m << 1) : (((m - 4) << 1) + 1);
            hwoff[g] = myrow * SW + blk * 16 + sl * 2 + odd;
        }
    const int abase = qrow * SW + (lane & 3) * 4;   // u16 idx; per kc add kc*16

    float cur[MT][2][4], nxt[MT][2][4];
#pragma unroll
    for (int mt = 0; mt < MT; mt++)
#pragma unroll
        for (int h8 = 0; h8 < 2; h8++) {
            const float* p = gp + mt * (16 * 256) + h8 * 8;
            float2 ab = *(const float2*)p;
            float2 cd = *(const float2*)(p + 8 * 256);
            cur[mt][h8][0] = ab.x; cur[mt][h8][1] = ab.y;
            cur[mt][h8][2] = cd.x; cur[mt][h8][3] = cd.y;
        }
    gp += dstep;

    float creg[MT][2];
#pragma unroll
    for (int mt = 0; mt < MT; mt++)
#pragma unroll
        for (int h8 = 0; h8 < 2; h8++) creg[mt][h8] = 0.0f;
    __syncthreads();

#define LSTM_STEP(RHI, RLO, WHI_, WLO_, CUR, NXT, TQ)                            \
    do {                                                                         \
        if ((TQ) + 1 < T) {                                                      \
            _Pragma("unroll") for (int mt = 0; mt < MT; mt++)                    \
            _Pragma("unroll") for (int h8 = 0; h8 < 2; h8++) {                   \
                const float* p = gp + mt * (16 * 256) + h8 * 8;                  \
                float2 ab = *(const float2*)p;                                   \
                float2 cd = *(const float2*)(p + 8 * 256);                       \
                NXT[mt][h8][0] = ab.x; NXT[mt][h8][1] = ab.y;                    \
                NXT[mt][h8][2] = cd.x; NXT[mt][h8][3] = cd.y;                    \
            }                                                                    \
        }                                                                        \
        float acc1[MT][2][4], acc2[MT][2][4];                                    \
        if (SACC) {                                                              \
            _Pragma("unroll") for (int mt = 0; mt < MT; mt++)                    \
            _Pragma("unroll") for (int h8 = 0; h8 < 2; h8++)                     \
            _Pragma("unroll") for (int q = 0; q < 4; q++) {                      \
                acc1[mt][h8][q] = 0.0f; acc2[mt][h8][q] = 0.0f;                  \
            }                                                                    \
        }                                                                        \
        _Pragma("unroll") for (int kc = 0; kc < 4; kc++) {                       \
            uint32_t Ah[MT][4], Al[MT][4];                                       \
            _Pragma("unroll") for (int mt = 0; mt < MT; mt++) {                  \
                int base = abase + mt * 16 * SW + kc * 16;                       \
                uint2 v0 = *(const uint2*)&RHI[base];                            \
                uint2 v1 = *(const uint2*)&RHI[base + 8 * SW];                   \
                Ah[mt][0] = v0.x; Ah[mt][2] = v0.y;                              \
                Ah[mt][1] = v1.x; Ah[mt][3] = v1.y;                              \
                uint2 w0 = *(const uint2*)&RLO[base];                            \
                uint2 w1 = *(const uint2*)&RLO[base + 8 * SW];                   \
                Al[mt][0] = w0.x; Al[mt][2] = w0.y;                              \
                Al[mt][1] = w1.x; Al[mt][3] = w1.y;                              \
            }                                                                    \
            _Pragma("unroll") for (int mt = 0; mt < MT; mt++)                    \
            _Pragma("unroll") for (int h8 = 0; h8 < 2; h8++) {                   \
                mma_bf16(CUR[mt][h8], Ah[mt], &Bh[kc][h8 * 2]);                  \
                float* t1 = SACC ? acc1[mt][h8] : CUR[mt][h8];                   \
                float* t2 = SACC ? acc2[mt][h8] : CUR[mt][h8];                   \
                mma_bf16(t1, Ah[mt], &Bl[kc][h8 * 2]);                           \
                mma_bf16(t2, Al[mt], &Bh[kc][h8 * 2]);                           \
            }                                                                    \
        }                                                                        \
        _Pragma("unroll") for (int mt = 0; mt < MT; mt++)                        \
        _Pragma("unroll") for (int h8 = 0; h8 < 2; h8++) {                       \
            int g = mt * 2 + h8;                                                 \
            float cc0 = CUR[mt][h8][0], cc1 = CUR[mt][h8][1];                    \
            float cc2 = CUR[mt][h8][2], cc3 = CUR[mt][h8][3];                    \
            if (SACC) {                                                          \
                cc0 += acc1[mt][h8][0] + acc2[mt][h8][0];                        \
                cc1 += acc1[mt][h8][1] + acc2[mt][h8][1];                        \
                cc2 += acc1[mt][h8][2] + acc2[mt][h8][2];                        \
                cc3 += acc1[mt][h8][3] + acc2[mt][h8][3];                        \
            }                                                                    \
            float s0v = par ? cc0 : cc2;                                         \
            float s1v = par ? cc1 : cc3;                                         \
            float r0 = __shfl_xor_sync(0xFFFFFFFFu, s0v, 1);                     \
            float r1 = __shfl_xor_sync(0xFFFFFFFFu, s1v, 1);                     \
            float iv, fv, gv, ov;                                                \
            if (!par) { iv = cc0; fv = cc1; gv = r0; ov = r1; }                  \
            else      { iv = r0;  fv = r1;  gv = cc2; ov = cc3; }                \
            float si = fmaf(0.5f, tanh_ap(0.5f * iv), 0.5f);                     \
            float sf = fmaf(0.5f, tanh_ap(0.5f * fv), 0.5f);                     \
            float so = fmaf(0.5f, tanh_ap(0.5f * ov), 0.5f);                     \
            float tg = tanh_ap(gv);                                              \
            float cst = sf * creg[mt][h8] + si * tg;                             \
            creg[mt][h8] = cst;                                                  \
            float hv = so * tanh_ap(cst);                                        \
            uint16_t hb, lb;                                                     \
            split1(hv, hb, lb);                                                  \
            WHI_[hwoff[g]] = hb;                                                 \
            WLO_[hwoff[g]] = lb;                                                 \
            op[ooff[g]] = hv;                                                    \
        }                                                                        \
        gp += dstep;                                                             \
        op += dOT;                                                               \
        __syncthreads();                                                         \
    } while (0)

    for (int t = 0; t < T; t += 2) {
        LSTM_STEP(hHi0, hLo0, hHi1, hLo1, cur, nxt, t);
        LSTM_STEP(hHi1, hLo1, hHi0, hLo0, nxt, cur, t + 1);
    }
#undef LSTM_STEP
}

// ---------------- launch ----------------
extern "C" void kernel_launch(void* const* d_in, const int* in_sizes, int n_in,
                              void* d_out, int out_size) {
    const float* img    = (const float*)d_in[0];
    const float* hWihF  = (const float*)d_in[1];
    const float* hWhhF  = (const float*)d_in[2];
    const float* hbihF  = (const float*)d_in[3];
    const float* hbhhF  = (const float*)d_in[4];
    const float* hWihB  = (const float*)d_in[5];
    const float* hWhhB  = (const float*)d_in[6];
    const float* hbihB  = (const float*)d_in[7];
    const float* hbhhB  = (const float*)d_in[8];
    const float* vWihF  = (const float*)d_in[9];
    const float* vWhhF  = (const float*)d_in[10];
    const float* vbihF  = (const float*)d_in[11];
    const float* vbhhF  = (const float*)d_in[12];
    const float* vWihB  = (const float*)d_in[13];
    const float* vWhhB  = (const float*)d_in[14];
    const float* vbihB  = (const float*)d_in[15];
    const float* vbhhB  = (const float*)d_in[16];
    float* out = (float*)d_out;

    auto hG = gx_gemm<64, true>;     // packed g_xh input, PRMT unpack
    auto vG = gx_gemm<128, false>;   // fp32 g_vbuf input, split4
    auto hR = lstm_recur_mma<false, 256, 1024, 16, 1024, 8, 262144>;
    auto vR = lstm_recur_mma<true, 128, 2048, 32, 262144, (1 << 28), 0>;

    const int smemHG = 128 * 64 * 4 + 4 * 128 * (64 + 8) * 2 + 512;    // 107,008 B
    const int smemVG = 128 * 128 * 4 + 4 * 128 * (128 + 8) * 2 + 512;  // 205,312 B
    const int smemR = 2 * 256 * 72 * 2;                                //  73,728 B
    cudaFuncSetAttribute(hG, cudaFuncAttributeMaxDynamicSharedMemorySize, smemHG);
    cudaFuncSetAttribute(vG, cudaFuncAttributeMaxDynamicSharedMemorySize, smemVG);
    cudaFuncSetAttribute(hR, cudaFuncAttributeMaxDynamicSharedMemorySize, smemR);
    cudaFuncSetAttribute(vR, cudaFuncAttributeMaxDynamicSharedMemorySize, smemR);

    // 1) img -> packed g_xh plane
    transpose_in_k<<<dim3(WW / 32, DD / 32, HH * BB), dim3(32, 8)>>>(img);

    // 2) gxh (permuted, bias folded; packed input, PRMT unpack)
    hG<<<dim3(37, 4), 256, smemHG>>>(hWihF, hWihB, hbihF, hbhhF, hbihB, hbhhB, 2048);

    // 3) capture-alignment probe (keeps hR at launch #4 for ncu)
    probe_k<<<1, 32>>>();

    // 4) horizontal mma recurrence -> g_vbuf (fp32, single STG.32 per output)
    hR<<<dim3(64, 2), 512, smemR>>>(hWhhF, hWhhB);

    // 5) gxv (fp32 stage + split4)
    vG<<<dim3(37, 4), 256, smemVG>>>(vWihF, vWihB, vbihF, vbhhF, vbihB, vbhhB, 2048);

    // 6) vertical mma recurrence -> g_vout
    vR<<<dim3(64, 2), 512, smemR>>>(vWhhF, vWhhB);

    // 7) g_vout -> out
    transpose_out_k<<<dim3(WW / 32, 128 / 32, HH * BB), dim3(32, 8)>>>(out);
}